// round 1
// baseline (speedup 1.0000x reference)
#include <cuda_runtime.h>
#include <math.h>

// ---------------- problem constants ----------------
#define NS    4096          // N samples
#define LS    16            // L tokens
#define DE    768           // D embedding
#define NHN   4             // heads (name attn)
#define DHN   192           // head dim (name attn)
#define HD    1024          // H
#define NLAY  4             // NL
#define NCLS  16            // C
#define XFD   256           // XF

// ---------------- scratch (device globals; no cudaMalloc allowed) ----------------
__device__ float g_qkv[(size_t)NS * LS * 3 * DE];   // 65536 x 2304
__device__ float g_attnsum[(size_t)NS * DE];        // 4096 x 768  (sum of o_s over masked q)
__device__ float g_proj[(size_t)NS * DE];           // 4096 x 768  (name_emb)
__device__ float g_h[(size_t)NS * HD];              // 4096 x 1024
__device__ float g_t1[(size_t)NS * 2 * HD];         // 4096 x 2048
__device__ float g_ta[(size_t)NS * HD];             // 4096 x 1024
__device__ float g_tv[(size_t)NS * HD];             // 4096 x 1024

// ---------------- generic SGEMM: C[M,N] = A[M,K] @ B[N,K]^T + bias ----------------
// AMODE: 0 = direct A, 1 = gathered A rows via tok[] (rows of A=wte), 2 = split A (A|A2 at K1)
// rowscale (optional): bias term becomes rowscale[m]*bias[n]
#define BMT 128
#define BNT 128
#define BKT 8

template<int AMODE, bool RELU>
__global__ __launch_bounds__(256) void sgemm_kernel(
    int M, int N, int K, int K1,
    const float* __restrict__ A, const float* __restrict__ A2,
    const int* __restrict__ tok,
    const float* __restrict__ B,
    const float* __restrict__ bias,
    const int* __restrict__ rowscale,
    float* __restrict__ C)
{
    __shared__ float As[BKT][BMT];
    __shared__ float Bs[BKT][BNT];
    __shared__ int toks[BMT];

    const int tid = threadIdx.x;
    const int bm  = blockIdx.y * BMT;
    const int bn  = blockIdx.x * BNT;

    if (AMODE == 1) {
        if (tid < BMT) toks[tid] = tok[bm + tid];
        __syncthreads();
    }

    const int lrow = tid >> 1;          // 0..127
    const int lcol = (tid & 1) * 4;     // 0 or 4
    const int ty   = tid >> 4;          // 0..15
    const int tx   = tid & 15;          // 0..15

    float acc[8][8];
#pragma unroll
    for (int i = 0; i < 8; i++)
#pragma unroll
        for (int j = 0; j < 8; j++) acc[i][j] = 0.f;

    for (int k0 = 0; k0 < K; k0 += BKT) {
        const int kk = k0 + lcol;
        float4 av;
        if (AMODE == 0) {
            av = *reinterpret_cast<const float4*>(A + (size_t)(bm + lrow) * K + kk);
        } else if (AMODE == 1) {
            av = *reinterpret_cast<const float4*>(A + (size_t)toks[lrow] * K + kk);
        } else {
            if (kk < K1)
                av = *reinterpret_cast<const float4*>(A + (size_t)(bm + lrow) * K1 + kk);
            else
                av = *reinterpret_cast<const float4*>(A2 + (size_t)(bm + lrow) * (K - K1) + (kk - K1));
        }
        const float4 bv = *reinterpret_cast<const float4*>(B + (size_t)(bn + lrow) * K + kk);

        As[lcol + 0][lrow] = av.x; As[lcol + 1][lrow] = av.y;
        As[lcol + 2][lrow] = av.z; As[lcol + 3][lrow] = av.w;
        Bs[lcol + 0][lrow] = bv.x; Bs[lcol + 1][lrow] = bv.y;
        Bs[lcol + 2][lrow] = bv.z; Bs[lcol + 3][lrow] = bv.w;
        __syncthreads();

#pragma unroll
        for (int k = 0; k < BKT; k++) {
            const float4 a0 = *reinterpret_cast<const float4*>(&As[k][ty * 8]);
            const float4 a1 = *reinterpret_cast<const float4*>(&As[k][ty * 8 + 4]);
            const float4 b0 = *reinterpret_cast<const float4*>(&Bs[k][tx * 8]);
            const float4 b1 = *reinterpret_cast<const float4*>(&Bs[k][tx * 8 + 4]);
            const float ra[8] = {a0.x, a0.y, a0.z, a0.w, a1.x, a1.y, a1.z, a1.w};
            const float rb[8] = {b0.x, b0.y, b0.z, b0.w, b1.x, b1.y, b1.z, b1.w};
#pragma unroll
            for (int i = 0; i < 8; i++)
#pragma unroll
                for (int j = 0; j < 8; j++)
                    acc[i][j] += ra[i] * rb[j];
        }
        __syncthreads();
    }

#pragma unroll
    for (int i = 0; i < 8; i++) {
        const int m = bm + ty * 8 + i;
        float rs = 1.f;
        if (rowscale) rs = (float)rowscale[m];
#pragma unroll
        for (int j = 0; j < 8; j++) {
            const int n = bn + tx * 8 + j;
            float v = acc[i][j] + rs * bias[n];
            if (RELU) v = fmaxf(v, 0.f);
            C[(size_t)m * N + n] = v;
        }
    }
}

// ---------------- name attention (S=16, 4 heads, dh=192), masked, q-summed ----------------
// One block per (head, sample); 192 threads (one per head-dim channel).
// Writes attnsum[b, h*192+d] = sum_{s<len} o[s, h, d]  (pre out-projection).
__global__ __launch_bounds__(192) void name_attn_kernel(
    const float* __restrict__ qkv, const int* __restrict__ lens,
    float* __restrict__ attnsum)
{
    __shared__ float Qs[LS][DHN];
    __shared__ float Ks[LS][DHN];
    __shared__ float Vs[LS][DHN];
    __shared__ float sc[LS][LS + 1];

    const int h = blockIdx.x;   // 0..3
    const int b = blockIdx.y;   // 0..4095
    const int d = threadIdx.x;  // 0..191

    const float* base = qkv + (size_t)b * LS * (3 * DE) + h * DHN + d;
#pragma unroll
    for (int s = 0; s < LS; s++) {
        Qs[s][d] = base[s * (3 * DE)];
        Ks[s][d] = base[s * (3 * DE) + DE];
        Vs[s][d] = base[s * (3 * DE) + 2 * DE];
    }
    __syncthreads();

    const int warp = d >> 5, lane = d & 31;
    const float scale = 1.0f / sqrtf((float)DHN);
    for (int p = warp; p < LS * LS; p += 6) {
        const int q = p >> 4, j = p & 15;
        float s = 0.f;
#pragma unroll
        for (int i = 0; i < 6; i++) s += Qs[q][lane + 32 * i] * Ks[j][lane + 32 * i];
#pragma unroll
        for (int o = 16; o; o >>= 1) s += __shfl_down_sync(0xffffffffu, s, o);
        if (lane == 0) sc[q][j] = s * scale;
    }
    __syncthreads();

    const int len = lens[b];
    if (d < LS) {
        float row[LS];
        float mx = -1e30f;
#pragma unroll
        for (int j = 0; j < LS; j++) {
            row[j] = (j < len) ? sc[d][j] : -1e9f;
            mx = fmaxf(mx, row[j]);
        }
        float sum = 0.f;
#pragma unroll
        for (int j = 0; j < LS; j++) { row[j] = expf(row[j] - mx); sum += row[j]; }
        const float inv = 1.f / sum;
#pragma unroll
        for (int j = 0; j < LS; j++) sc[d][j] = row[j] * inv;
    }
    __syncthreads();

    float accum = 0.f;
    for (int s = 0; s < len; s++) {   // only q positions inside the mask are summed
        float o = 0.f;
#pragma unroll
        for (int j = 0; j < LS; j++) o += sc[s][j] * Vs[j][d];
        accum += o;
    }
    attnsum[(size_t)b * DE + h * DHN + d] = accum;
}

// ---------------- residual + LayerNorm (in place on h): h = LN(h + a)*g + b ----------------
__device__ __forceinline__ float block_reduce_sum(float v) {
    __shared__ float red[8];
    const int lane = threadIdx.x & 31, warp = threadIdx.x >> 5;
#pragma unroll
    for (int o = 16; o; o >>= 1) v += __shfl_down_sync(0xffffffffu, v, o);
    if (lane == 0) red[warp] = v;
    __syncthreads();
    v = (threadIdx.x < 8) ? red[threadIdx.x] : 0.f;
    if (warp == 0)
#pragma unroll
        for (int o = 4; o; o >>= 1) v += __shfl_down_sync(0xffffffffu, v, o);
    return v;  // valid on thread 0
}

__global__ __launch_bounds__(256) void resid_ln_kernel(
    float* __restrict__ h, const float* __restrict__ a,
    const float* __restrict__ g, const float* __restrict__ b)
{
    const int row = blockIdx.x;
    const int t = threadIdx.x;
    float v[4];
    float s = 0.f;
#pragma unroll
    for (int i = 0; i < 4; i++) {
        const int c = t + 256 * i;
        v[i] = h[(size_t)row * HD + c] + a[(size_t)row * HD + c];
        s += v[i];
    }
    s = block_reduce_sum(s);
    __shared__ float mean_s, rstd_s;
    if (t == 0) mean_s = s * (1.f / HD);
    __syncthreads();
    const float m = mean_s;
    float s2 = 0.f;
#pragma unroll
    for (int i = 0; i < 4; i++) { const float dd = v[i] - m; s2 += dd * dd; }
    s2 = block_reduce_sum(s2);
    if (t == 0) rstd_s = rsqrtf(s2 * (1.f / HD) + 1e-5f);
    __syncthreads();
    const float r = rstd_s;
#pragma unroll
    for (int i = 0; i < 4; i++) {
        const int c = t + 256 * i;
        h[(size_t)row * HD + c] = (v[i] - m) * r * g[c] + b[c];
    }
}

// ---------------- classifier head: out[m,c] = h[m] . cls_w[c] + cls_b[c] ----------------
__global__ __launch_bounds__(512) void cls_kernel(
    const float* __restrict__ h, const float* __restrict__ w,
    const float* __restrict__ b, float* __restrict__ out)
{
    const int m = blockIdx.x;
    const int c = threadIdx.x >> 5;     // 16 warps = 16 classes
    const int lane = threadIdx.x & 31;
    const float* hr = h + (size_t)m * HD;
    const float* wr = w + (size_t)c * HD;
    float s = 0.f;
#pragma unroll
    for (int i = lane; i < HD; i += 32) s += hr[i] * wr[i];
#pragma unroll
    for (int o = 16; o; o >>= 1) s += __shfl_down_sync(0xffffffffu, s, o);
    if (lane == 0) out[(size_t)m * NCLS + c] = s + b[c];
}

// ---------------- orchestration ----------------
extern "C" void kernel_launch(void* const* d_in, const int* in_sizes, int n_in,
                              void* d_out, int out_size)
{
    const int*   name_tokens = (const int*)d_in[0];
    const int*   name_lens   = (const int*)d_in[1];
    const float* x_feats     = (const float*)d_in[2];
    const float* wte         = (const float*)d_in[3];
    const float* mha_in_w    = (const float*)d_in[4];
    const float* mha_in_b    = (const float*)d_in[5];
    const float* mha_out_w   = (const float*)d_in[6];
    const float* mha_out_b   = (const float*)d_in[7];
    const float* bott_w      = (const float*)d_in[8];
    const float* bott_b      = (const float*)d_in[9];
    const float* enc_in_w    = (const float*)d_in[10];
    const float* enc_in_b    = (const float*)d_in[11];
    const float* enc_out_w   = (const float*)d_in[12];
    const float* enc_out_b   = (const float*)d_in[13];
    const float* enc_ln1_g   = (const float*)d_in[14];
    const float* enc_ln1_b   = (const float*)d_in[15];
    const float* enc_ln2_g   = (const float*)d_in[16];
    const float* enc_ln2_b   = (const float*)d_in[17];
    const float* enc_ff1_w   = (const float*)d_in[18];
    const float* enc_ff1_b   = (const float*)d_in[19];
    const float* enc_ff2_w   = (const float*)d_in[20];
    const float* enc_ff2_b   = (const float*)d_in[21];
    const float* cls_w       = (const float*)d_in[22];
    const float* cls_b       = (const float*)d_in[23];
    float* out = (float*)d_out;

    float *qkv, *attnsum, *proj, *h, *t1, *ta, *tv;
    cudaGetSymbolAddress((void**)&qkv,     g_qkv);
    cudaGetSymbolAddress((void**)&attnsum, g_attnsum);
    cudaGetSymbolAddress((void**)&proj,    g_proj);
    cudaGetSymbolAddress((void**)&h,       g_h);
    cudaGetSymbolAddress((void**)&t1,      g_t1);
    cudaGetSymbolAddress((void**)&ta,      g_ta);
    cudaGetSymbolAddress((void**)&tv,      g_tv);

    const int MQ = NS * LS;          // 65536
    const int KQ = DE;               // 768
    const int NQ = 3 * DE;           // 2304

    // 1. qkv = gather(wte, tokens) @ mha_in_w^T + mha_in_b    [65536 x 2304]
    sgemm_kernel<1, false><<<dim3(NQ / BNT, MQ / BMT), 256>>>(
        MQ, NQ, KQ, 0, wte, nullptr, name_tokens, mha_in_w, mha_in_b, nullptr, qkv);

    // 2. masked name attention, summed over valid q positions -> attnsum [4096 x 768]
    name_attn_kernel<<<dim3(NHN, NS), 192>>>(qkv, name_lens, attnsum);

    // 3. name_emb = attnsum @ mha_out_w^T + len * mha_out_b   [4096 x 768]
    sgemm_kernel<0, false><<<dim3(DE / BNT, NS / BMT), 256>>>(
        NS, DE, DE, 0, attnsum, nullptr, nullptr, mha_out_w, mha_out_b, name_lens, proj);

    // 4. x = [x_feats | name_emb] @ bott_w^T + bott_b         [4096 x 1024]
    sgemm_kernel<2, false><<<dim3(HD / BNT, NS / BMT), 256>>>(
        NS, HD, XFD + DE, XFD, x_feats, proj, nullptr, bott_w, bott_b, nullptr, h);

    // 5. encoder layers (seq len 1 => attention == V/out projections only)
    for (int l = 0; l < NLAY; l++) {
        const float* wv = enc_in_w + (size_t)l * 3 * HD * HD + (size_t)2 * HD * HD;
        const float* bv = enc_in_b + (size_t)l * 3 * HD + 2 * HD;
        sgemm_kernel<0, false><<<dim3(HD / BNT, NS / BMT), 256>>>(
            NS, HD, HD, 0, h, nullptr, nullptr, wv, bv, nullptr, tv);
        sgemm_kernel<0, false><<<dim3(HD / BNT, NS / BMT), 256>>>(
            NS, HD, HD, 0, tv, nullptr, nullptr,
            enc_out_w + (size_t)l * HD * HD, enc_out_b + (size_t)l * HD, nullptr, ta);
        resid_ln_kernel<<<NS, 256>>>(h, ta, enc_ln1_g + (size_t)l * HD, enc_ln1_b + (size_t)l * HD);

        sgemm_kernel<0, true><<<dim3(2 * HD / BNT, NS / BMT), 256>>>(
            NS, 2 * HD, HD, 0, h, nullptr, nullptr,
            enc_ff1_w + (size_t)l * 2 * HD * HD, enc_ff1_b + (size_t)l * 2 * HD, nullptr, t1);
        sgemm_kernel<0, false><<<dim3(HD / BNT, NS / BMT), 256>>>(
            NS, HD, 2 * HD, 0, t1, nullptr, nullptr,
            enc_ff2_w + (size_t)l * HD * 2 * HD, enc_ff2_b + (size_t)l * HD, nullptr, ta);
        resid_ln_kernel<<<NS, 256>>>(h, ta, enc_ln2_g + (size_t)l * HD, enc_ln2_b + (size_t)l * HD);
    }

    // 6. classifier head -> out [4096 x 16]
    cls_kernel<<<NS, 512>>>(h, cls_w, cls_b, out);
}